// round 3
// baseline (speedup 1.0000x reference)
#include <cuda_runtime.h>
#include <math.h>

#define HH 1024
#define LL 128
#define VOCAB 50257

// ---------------- device scratch (no allocations allowed) ----------------
__device__ float g_scores[LL];
__device__ float g_attn[HH];
__device__ float g_gru_in[HH];
__device__ float g_hnew[HH];
__device__ float g_ghr[HH], g_ghz[HH], g_ghn[HH];
__device__ float g_bmax[1024], g_bsum[1024];
__device__ float g_lse;
__device__ unsigned g_arrive = 0;
__device__ unsigned g_gen = 0;

__device__ __forceinline__ float warp_sum(float v) {
#pragma unroll
    for (int o = 16; o > 0; o >>= 1) v += __shfl_down_sync(0xffffffffu, v, o);
    return v;
}

// sense-reversing software grid barrier (all blocks co-resident: grid = #SMs)
__device__ __forceinline__ void grid_bar(unsigned nb) {
    __syncthreads();
    if (threadIdx.x == 0) {
        __threadfence();
        unsigned gen = *(volatile unsigned*)&g_gen;
        if (atomicAdd(&g_arrive, 1u) == nb - 1u) {
            *(volatile unsigned*)&g_arrive = 0u;
            __threadfence();
            *(volatile unsigned*)&g_gen = gen + 1u;
        } else {
            while (*(volatile unsigned*)&g_gen == gen) {}
        }
        __threadfence();
    }
    __syncthreads();
}

__device__ __forceinline__ void lse_combine(float& M, float& S, float m2, float s2) {
    if (m2 > M) { S = S * expf(M - m2) + s2; M = m2; }
    else        { S += s2 * expf(m2 - M); }
}

// Prefetch nrows rows (4KB each) of out_W into L2. No register writeback,
// so the warp can arrive at the next barrier immediately; fetches overlap.
__device__ __forceinline__ void prefetch_rows(const float* base, int row0,
                                              int nrows, int lane) {
    const char* p = (const char*)base + (size_t)row0 * 4096;
    const size_t total = (size_t)nrows * 4096;
    for (size_t off = (size_t)lane * 128; off < total; off += 32 * 128)
        asm volatile("prefetch.global.L2 [%0];" :: "l"(p + off));
}

__global__ void __launch_bounds__(1024, 1)
fused_decoder(const int* __restrict__ ids,
              const float* __restrict__ hidden,
              const float* __restrict__ enc,
              const float* __restrict__ emb,
              const float* __restrict__ attn_W,
              const float* __restrict__ attn_b,
              const float* __restrict__ comb_W,
              const float* __restrict__ comb_b,
              const float* __restrict__ W_ih,
              const float* __restrict__ W_hh,
              const float* __restrict__ b_ih,
              const float* __restrict__ b_hh,
              const float* __restrict__ out_W,
              const float* __restrict__ out_b,
              float* __restrict__ out) {
    const unsigned nb = gridDim.x;
    const int t = threadIdx.x, wid = t >> 5, lane = t & 31, bid = blockIdx.x;
    const int task = wid * (int)nb + bid;   // warp-major: spreads tasks across SMs
    const int gw   = bid * 32 + wid;        // block-major: row locality for logits
    const int totW = (int)nb * 32;

    __shared__ float s_red[1024];
    __shared__ float s_w[LL];
    __shared__ float s_m[2];
    __shared__ float s_bm[32], s_bs[32];

    const size_t qb = (size_t)ids[0] * HH;
    const float4* q4 = (const float4*)(emb + qb);
    const float4* h4 = (const float4*)hidden;

    // ---------------- Phase 0: gh = W_hh @ h (+bias), and attention scores ----
    if (task < HH) {
        const int j = task;
        const float4* wr = (const float4*)(W_hh + (size_t)j * HH);
        const float4* wz = (const float4*)(W_hh + (size_t)(j + HH) * HH);
        const float4* wn = (const float4*)(W_hh + (size_t)(j + 2 * HH) * HH);
        float ar = 0.f, az = 0.f, an = 0.f;
#pragma unroll
        for (int i = 0; i < 8; i++) {
            const int idx = lane + 32 * i;
            const float4 hv = h4[idx];
            float4 v;
            v = wr[idx]; ar += v.x*hv.x + v.y*hv.y + v.z*hv.z + v.w*hv.w;
            v = wz[idx]; az += v.x*hv.x + v.y*hv.y + v.z*hv.z + v.w*hv.w;
            v = wn[idx]; an += v.x*hv.x + v.y*hv.y + v.z*hv.z + v.w*hv.w;
        }
        ar = warp_sum(ar); az = warp_sum(az); an = warp_sum(an);
        if (lane == 0) {
            g_ghr[j] = ar + b_hh[j];
            g_ghz[j] = az + b_hh[j + HH];
            g_ghn[j] = an + b_hh[j + 2 * HH];
        }
    } else if (task < HH + LL) {
        const int l = task - HH;
        const float4* w = (const float4*)(attn_W + (size_t)l * 2 * HH);
        float acc = 0.f;
#pragma unroll
        for (int i = 0; i < 8; i++) {
            const int idx = lane + 32 * i;
            float4 a = w[idx],       b = q4[idx];
            acc += a.x*b.x + a.y*b.y + a.z*b.z + a.w*b.w;
            float4 c = w[idx + 256], d = h4[idx];
            acc += c.x*d.x + c.y*d.y + c.z*d.z + c.w*d.w;
        }
        acc = warp_sum(acc);
        if (lane == 0) g_scores[l] = acc + attn_b[l];
    } else {
        const int idx = task - (HH + LL);          // [0, 3584)
        prefetch_rows(out_W, 2 * idx, 2, lane);    // rows [0, 7168)
    }
    grid_bar(nb);

    // ---------------- Phase 1: softmax + attn_applied (blocks 0..7) ----------
    if (bid < 8) {
        float sc = (t < LL) ? g_scores[t] : -INFINITY;
        if (t < LL) {
            float v = sc;
#pragma unroll
            for (int o = 16; o > 0; o >>= 1) v = fmaxf(v, __shfl_down_sync(0xffffffffu, v, o));
            if (lane == 0) s_bm[wid] = v;
        }
        __syncthreads();
        if (t == 0) s_m[0] = fmaxf(fmaxf(s_bm[0], s_bm[1]), fmaxf(s_bm[2], s_bm[3]));
        __syncthreads();
        float e = 0.f;
        if (t < LL) {
            e = expf(sc - s_m[0]);
            float v = warp_sum(e);
            if (lane == 0) s_bs[wid] = v;
        }
        __syncthreads();
        if (t == 0) s_m[1] = 1.f / (s_bs[0] + s_bs[1] + s_bs[2] + s_bs[3]);
        __syncthreads();
        if (t < LL) {
            s_w[t] = e * s_m[1];
            if (bid == 0) out[VOCAB + HH + t] = s_w[t];
        }
        __syncthreads();
        const int col = t & 127, lg = t >> 7;
        const int colg = bid * 128 + col;
        float acc = 0.f;
#pragma unroll
        for (int k = 0; k < 16; k++) {
            const int l = lg * 16 + k;
            acc += s_w[l] * enc[(size_t)l * HH + colg];
        }
        s_red[t] = acc;
        __syncthreads();
        if (t < 128) {
            float a = 0.f;
#pragma unroll
            for (int k = 0; k < 8; k++) a += s_red[t + 128 * k];
            g_attn[colg] = a;
        }
    } else {
        const int idx = (bid - 8) * 32 + wid;          // [0, 4480)
        prefetch_rows(out_W, 7168 + idx, 1, lane);     // rows [7168, 11648)
    }
    grid_bar(nb);

    // ---------------- Phase 2: gru_in = relu([q; attn] @ comb_W.T + b) -------
    if (task < HH) {
        const int j = task;
        const float4* wr = (const float4*)(comb_W + (size_t)j * 2 * HH);
        const float4* a4 = (const float4*)g_attn;
        float acc = 0.f;
#pragma unroll
        for (int i = 0; i < 8; i++) {
            const int idx = lane + 32 * i;
            float4 a = wr[idx],       b = q4[idx];
            acc += a.x*b.x + a.y*b.y + a.z*b.z + a.w*b.w;
            float4 c = wr[idx + 256], d = a4[idx];
            acc += c.x*d.x + c.y*d.y + c.z*d.z + c.w*d.w;
        }
        acc = warp_sum(acc);
        if (lane == 0) g_gru_in[j] = fmaxf(acc + comb_b[j], 0.f);
    } else {
        const int idx = task - HH;                        // [0, 3712)
        prefetch_rows(out_W, 11648 + 2 * idx, 2, lane);   // rows [11648, 19072)
    }
    grid_bar(nb);

    // ---------------- Phase 3: gi = W_ih @ gru_in, + GRU gate math -----------
    if (task < HH) {
        const int j = task;
        const float4* wr = (const float4*)(W_ih + (size_t)j * HH);
        const float4* wz = (const float4*)(W_ih + (size_t)(j + HH) * HH);
        const float4* wn = (const float4*)(W_ih + (size_t)(j + 2 * HH) * HH);
        const float4* g4 = (const float4*)g_gru_in;
        float ar = 0.f, az = 0.f, an = 0.f;
#pragma unroll
        for (int i = 0; i < 8; i++) {
            const int idx = lane + 32 * i;
            const float4 gv = g4[idx];
            float4 v;
            v = wr[idx]; ar += v.x*gv.x + v.y*gv.y + v.z*gv.z + v.w*gv.w;
            v = wz[idx]; az += v.x*gv.x + v.y*gv.y + v.z*gv.z + v.w*gv.w;
            v = wn[idx]; an += v.x*gv.x + v.y*gv.y + v.z*gv.z + v.w*gv.w;
        }
        ar = warp_sum(ar); az = warp_sum(az); an = warp_sum(an);
        if (lane == 0) {
            const float ir  = ar + b_ih[j];
            const float iz  = az + b_ih[j + HH];
            const float inn = an + b_ih[j + 2 * HH];
            const float r = 1.f / (1.f + expf(-(ir + g_ghr[j])));
            const float z = 1.f / (1.f + expf(-(iz + g_ghz[j])));
            const float n = tanhf(inn + r * g_ghn[j]);
            const float hn = (1.f - z) * n + z * hidden[j];
            g_hnew[j] = hn;
            out[VOCAB + j] = hn;
        }
    } else {
        const int idx = task - HH;                        // [0, 3712)
        prefetch_rows(out_W, 19072 + 2 * idx, 2, lane);   // rows [19072, 26496)
    }
    grid_bar(nb);

    // ---------------- Phase 5: logits GEMV (206 MB) + online (max,sumexp) ----
    {
        float4 hv[8];
#pragma unroll
        for (int i = 0; i < 8; i++) hv[i] = ((const float4*)g_hnew)[lane + 32 * i];
        float m = -INFINITY, s = 0.f;
        for (int r = gw; r < VOCAB; r += totW) {
            const float4* wr = (const float4*)(out_W + (size_t)r * HH);
            float acc = 0.f;
#pragma unroll
            for (int i = 0; i < 8; i++) {
                const float4 a = wr[lane + 32 * i];
                acc += a.x*hv[i].x + a.y*hv[i].y + a.z*hv[i].z + a.w*hv[i].w;
            }
            acc = warp_sum(acc);
            if (lane == 0) {
                const float lg = acc + out_b[r];
                out[r] = lg;
                lse_combine(m, s, lg, 1.f);
            }
        }
        if (lane == 0) { s_bm[wid] = m; s_bs[wid] = s; }
        __syncthreads();
        if (t == 0) {
            float M = -INFINITY, S = 0.f;
#pragma unroll
            for (int k = 0; k < 32; k++) lse_combine(M, S, s_bm[k], s_bs[k]);
            g_bmax[bid] = M; g_bsum[bid] = S;
        }
    }
    grid_bar(nb);

    // ---------------- Phase 6: global LSE ------------------------------------
    if (bid == 0 && wid == 0) {
        float M = -INFINITY, S = 0.f;
        for (int i = lane; i < (int)nb; i += 32) lse_combine(M, S, g_bmax[i], g_bsum[i]);
#pragma unroll
        for (int o = 16; o > 0; o >>= 1) {
            float m2 = __shfl_down_sync(0xffffffffu, M, o);
            float s2 = __shfl_down_sync(0xffffffffu, S, o);
            lse_combine(M, S, m2, s2);
        }
        if (lane == 0) g_lse = M + logf(S);
    }
    grid_bar(nb);

    // ---------------- Phase 7: log_probs = logits - lse ----------------------
    {
        const float lse = g_lse;
        for (int i = bid * 1024 + t; i < VOCAB; i += (int)nb * 1024) out[i] -= lse;
    }
}

extern "C" void kernel_launch(void* const* d_in, const int* in_sizes, int n_in,
                              void* d_out, int out_size) {
    const int*   ids    = (const int*)  d_in[0];
    const float* hidden = (const float*)d_in[1];
    const float* enc    = (const float*)d_in[2];
    const float* emb    = (const float*)d_in[3];
    const float* attn_W = (const float*)d_in[4];
    const float* attn_b = (const float*)d_in[5];
    const float* comb_W = (const float*)d_in[6];
    const float* comb_b = (const float*)d_in[7];
    const float* W_ih   = (const float*)d_in[8];
    const float* W_hh   = (const float*)d_in[9];
    const float* b_ih   = (const float*)d_in[10];
    const float* b_hh   = (const float*)d_in[11];
    const float* out_W  = (const float*)d_in[12];
    const float* out_b  = (const float*)d_in[13];
    float* out = (float*)d_out;

    int dev = 0, nsm = 148;
    cudaGetDevice(&dev);
    cudaDeviceGetAttribute(&nsm, cudaDevAttrMultiProcessorCount, dev);

    fused_decoder<<<nsm, 1024>>>(ids, hidden, enc, emb, attn_W, attn_b,
                                 comb_W, comb_b, W_ih, W_hh, b_ih, b_hh,
                                 out_W, out_b, out);
}

// round 4
// speedup vs baseline: 1.0875x; 1.0875x over previous
#include <cuda_runtime.h>
#include <math.h>

#define HH 1024
#define LL 128
#define VOCAB 50257
#define RSTAGE 44                 // rows of out_W staged in SMEM per block
#define KMAX 10                   // max strided rows per warp

// ---------------- device scratch (no allocations allowed) ----------------
__device__ float g_scores[LL];
__device__ float g_attn[HH];
__device__ float g_gru_in[HH];
__device__ float g_hnew[HH];
__device__ float g_ghr[HH], g_ghz[HH], g_ghn[HH];
__device__ float g_bmax[1024], g_bsum[1024];
__device__ float g_lse;
__device__ unsigned g_arrive = 0;
__device__ unsigned g_gen = 0;

__device__ __forceinline__ float warp_sum(float v) {
#pragma unroll
    for (int o = 16; o > 0; o >>= 1) v += __shfl_down_sync(0xffffffffu, v, o);
    return v;
}

__device__ __forceinline__ void grid_bar(unsigned nb) {
    __syncthreads();
    if (threadIdx.x == 0) {
        __threadfence();
        unsigned gen = *(volatile unsigned*)&g_gen;
        if (atomicAdd(&g_arrive, 1u) == nb - 1u) {
            *(volatile unsigned*)&g_arrive = 0u;
            __threadfence();
            *(volatile unsigned*)&g_gen = gen + 1u;
        } else {
            while (*(volatile unsigned*)&g_gen == gen) {}
        }
        __threadfence();
    }
    __syncthreads();
}

__device__ __forceinline__ void lse_combine(float& M, float& S, float m2, float s2) {
    if (m2 > M) { S = S * expf(M - m2) + s2; M = m2; }
    else        { S += s2 * expf(m2 - M); }
}

// copy one 4KB row of out_W into SMEM (one warp)
__device__ __forceinline__ void stage_row(const float* __restrict__ out_W,
                                          float* s_stage, int bid, int j, int lane) {
    const float4* src = (const float4*)(out_W + (size_t)(bid * RSTAGE + j) * HH);
    float4* dst = (float4*)(s_stage + j * HH);
#pragma unroll
    for (int i = 0; i < 8; i++) dst[lane + 32 * i] = src[lane + 32 * i];
}

extern __shared__ float s_stage[];   // RSTAGE * HH floats (176KB)

__global__ void __launch_bounds__(1024, 1)
fused_decoder(const int* __restrict__ ids,
              const float* __restrict__ hidden,
              const float* __restrict__ enc,
              const float* __restrict__ emb,
              const float* __restrict__ attn_W,
              const float* __restrict__ attn_b,
              const float* __restrict__ comb_W,
              const float* __restrict__ comb_b,
              const float* __restrict__ W_ih,
              const float* __restrict__ W_hh,
              const float* __restrict__ b_ih,
              const float* __restrict__ b_hh,
              const float* __restrict__ out_W,
              const float* __restrict__ out_b,
              float* __restrict__ out) {
    const unsigned nb = gridDim.x;
    const int t = threadIdx.x, wid = t >> 5, lane = t & 31, bid = blockIdx.x;
    const int task = wid * (int)nb + bid;   // warp-major task id for serial phases
    const int gw   = bid * 32 + wid;        // global warp id for logits
    const int totW = (int)nb * 32;
    const int NSTAGED = (int)nb * RSTAGE;   // rows served from SMEM chip-wide
    const int NREM = VOCAB - NSTAGED;       // rows streamed from DRAM

    __shared__ float s_red[1024];
    __shared__ float s_h[HH];
    __shared__ float s_w[LL];
    __shared__ float s_m[2];
    __shared__ float s_bm[32], s_bs[32];
    __shared__ float s_wlog[32 * KMAX];
    __shared__ float s_stlog[RSTAGE];

    const size_t qb = (size_t)ids[0] * HH;
    const float4* q4 = (const float4*)(emb + qb);
    const float4* h4 = (const float4*)hidden;

    // ---------------- Phase 0: gh = W_hh@h (+bias) | attn scores | staging ---
    if (task < HH) {
        const int j = task;
        const float4* wr = (const float4*)(W_hh + (size_t)j * HH);
        const float4* wz = (const float4*)(W_hh + (size_t)(j + HH) * HH);
        const float4* wn = (const float4*)(W_hh + (size_t)(j + 2 * HH) * HH);
        float ar = 0.f, az = 0.f, an = 0.f;
#pragma unroll
        for (int i = 0; i < 8; i++) {
            const int idx = lane + 32 * i;
            const float4 hv = h4[idx];
            float4 v;
            v = wr[idx]; ar += v.x*hv.x + v.y*hv.y + v.z*hv.z + v.w*hv.w;
            v = wz[idx]; az += v.x*hv.x + v.y*hv.y + v.z*hv.z + v.w*hv.w;
            v = wn[idx]; an += v.x*hv.x + v.y*hv.y + v.z*hv.z + v.w*hv.w;
        }
        ar = warp_sum(ar); az = warp_sum(az); an = warp_sum(an);
        if (lane == 0) {
            g_ghr[j] = ar + b_hh[j];
            g_ghz[j] = az + b_hh[j + HH];
            g_ghn[j] = an + b_hh[j + 2 * HH];
        }
    } else if (task < HH + LL) {
        const int l = task - HH;
        const float4* w = (const float4*)(attn_W + (size_t)l * 2 * HH);
        float acc = 0.f;
#pragma unroll
        for (int i = 0; i < 8; i++) {
            const int idx = lane + 32 * i;
            float4 a = w[idx],       b = q4[idx];
            acc += a.x*b.x + a.y*b.y + a.z*b.z + a.w*b.w;
            float4 c = w[idx + 256], d = h4[idx];
            acc += c.x*d.x + c.y*d.y + c.z*d.z + c.w*d.w;
        }
        acc = warp_sum(acc);
        if (lane == 0) g_scores[l] = acc + attn_b[l];
    } else if (wid >= 8 && wid < 23) {        // always idle warps: stage rows 0..14
        stage_row(out_W, s_stage, bid, wid - 8, lane);
    }
    grid_bar(nb);

    // ---------------- Phase 1: softmax + attn_applied (blocks 0..7) ----------
    if (bid < 8) {
        float sc = (t < LL) ? g_scores[t] : -INFINITY;
        if (t < LL) {
            float v = sc;
#pragma unroll
            for (int o = 16; o > 0; o >>= 1) v = fmaxf(v, __shfl_down_sync(0xffffffffu, v, o));
            if (lane == 0) s_bm[wid] = v;
        }
        __syncthreads();
        if (t == 0) s_m[0] = fmaxf(fmaxf(s_bm[0], s_bm[1]), fmaxf(s_bm[2], s_bm[3]));
        __syncthreads();
        float e = 0.f;
        if (t < LL) {
            e = expf(sc - s_m[0]);
            float v = warp_sum(e);
            if (lane == 0) s_bs[wid] = v;
        }
        __syncthreads();
        if (t == 0) s_m[1] = 1.f / (s_bs[0] + s_bs[1] + s_bs[2] + s_bs[3]);
        __syncthreads();
        if (t < LL) {
            s_w[t] = e * s_m[1];
            if (bid == 0) out[VOCAB + HH + t] = s_w[t];
        }
        __syncthreads();
        const int col = t & 127, lg = t >> 7;
        const int colg = bid * 128 + col;
        float acc = 0.f;
#pragma unroll
        for (int k = 0; k < 16; k++) {
            const int l = lg * 16 + k;
            acc += s_w[l] * enc[(size_t)l * HH + colg];
        }
        s_red[t] = acc;
        __syncthreads();
        if (t < 128) {
            float a = 0.f;
#pragma unroll
            for (int k = 0; k < 8; k++) a += s_red[t + 128 * k];
            g_attn[colg] = a;
        }
    }
    grid_bar(nb);

    // ---------------- Phase 2: gru_in = relu([q; attn]@comb_W.T+b) | staging -
    if (task < HH) {
        const int j = task;
        const float4* wr = (const float4*)(comb_W + (size_t)j * 2 * HH);
        const float4* a4 = (const float4*)g_attn;
        float acc = 0.f;
#pragma unroll
        for (int i = 0; i < 8; i++) {
            const int idx = lane + 32 * i;
            float4 a = wr[idx],       b = q4[idx];
            acc += a.x*b.x + a.y*b.y + a.z*b.z + a.w*b.w;
            float4 c = wr[idx + 256], d = a4[idx];
            acc += c.x*d.x + c.y*d.y + c.z*d.z + c.w*d.w;
        }
        acc = warp_sum(acc);
        if (lane == 0) g_gru_in[j] = fmaxf(acc + comb_b[j], 0.f);
    } else if (wid >= 8 && wid < 23) {        // stage rows 15..29
        stage_row(out_W, s_stage, bid, wid - 8 + 15, lane);
    }
    grid_bar(nb);

    // ---------------- Phase 3: gi = W_ih@gru_in + GRU gates | staging --------
    if (task < HH) {
        const int j = task;
        const float4* wr = (const float4*)(W_ih + (size_t)j * HH);
        const float4* wz = (const float4*)(W_ih + (size_t)(j + HH) * HH);
        const float4* wn = (const float4*)(W_ih + (size_t)(j + 2 * HH) * HH);
        const float4* g4 = (const float4*)g_gru_in;
        float ar = 0.f, az = 0.f, an = 0.f;
#pragma unroll
        for (int i = 0; i < 8; i++) {
            const int idx = lane + 32 * i;
            const float4 gv = g4[idx];
            float4 v;
            v = wr[idx]; ar += v.x*gv.x + v.y*gv.y + v.z*gv.z + v.w*gv.w;
            v = wz[idx]; az += v.x*gv.x + v.y*gv.y + v.z*gv.z + v.w*gv.w;
            v = wn[idx]; an += v.x*gv.x + v.y*gv.y + v.z*gv.z + v.w*gv.w;
        }
        ar = warp_sum(ar); az = warp_sum(az); an = warp_sum(an);
        if (lane == 0) {
            const float ir  = ar + b_ih[j];
            const float iz  = az + b_ih[j + HH];
            const float inn = an + b_ih[j + 2 * HH];
            const float r = 1.f / (1.f + expf(-(ir + g_ghr[j])));
            const float z = 1.f / (1.f + expf(-(iz + g_ghz[j])));
            const float n = tanhf(inn + r * g_ghn[j]);
            const float hn = (1.f - z) * n + z * hidden[j];
            g_hnew[j] = hn;
            out[VOCAB + j] = hn;
        }
    } else if (wid >= 8 && wid < 22) {        // stage rows 30..43
        stage_row(out_W, s_stage, bid, wid - 8 + 30, lane);
    }
    grid_bar(nb);

    // ---------------- Phase 5: logits GEMV (DRAM strided + SMEM staged) ------
    {
        if (t < 256) ((float4*)s_h)[t] = ((const float4*)g_hnew)[t];
        if (t < 32 * KMAX) s_wlog[t] = -INFINITY;
        __syncthreads();
        const float4* h4s = (const float4*)s_h;

        // DRAM-streamed rows
        for (int k = 0; k < KMAX; k++) {
            const int r = gw + k * totW;
            if (r < NREM) {
                const int row = NSTAGED + r;
                const float4* wr = (const float4*)(out_W + (size_t)row * HH);
                float acc = 0.f;
#pragma unroll
                for (int i = 0; i < 8; i++) {
                    const int idx = lane + 32 * i;
                    const float4 a = wr[idx], b = h4s[idx];
                    acc += a.x*b.x + a.y*b.y + a.z*b.z + a.w*b.w;
                }
                acc = warp_sum(acc);
                if (lane == 0) s_wlog[wid * KMAX + k] = acc + out_b[row];
            }
        }
        // SMEM-staged rows
        for (int j = wid; j < RSTAGE; j += 32) {
            const float4* sr = (const float4*)(s_stage + j * HH);
            float acc = 0.f;
#pragma unroll
            for (int i = 0; i < 8; i++) {
                const int idx = lane + 32 * i;
                const float4 a = sr[idx], b = h4s[idx];
                acc += a.x*b.x + a.y*b.y + a.z*b.z + a.w*b.w;
            }
            acc = warp_sum(acc);
            if (lane == 0) s_stlog[j] = acc + out_b[bid * RSTAGE + j];
        }
        __syncthreads();
        // block-level (max, sumexp) over all this block's logits
        if (wid == 0) {
            float M = -INFINITY, S = 0.f;
            for (int i = lane; i < 32 * KMAX + RSTAGE; i += 32) {
                const float v = (i < 32 * KMAX) ? s_wlog[i] : s_stlog[i - 32 * KMAX];
                if (v > -INFINITY) lse_combine(M, S, v, 1.f);
            }
#pragma unroll
            for (int o = 16; o > 0; o >>= 1) {
                float m2 = __shfl_down_sync(0xffffffffu, M, o);
                float s2 = __shfl_down_sync(0xffffffffu, S, o);
                lse_combine(M, S, m2, s2);
            }
            if (lane == 0) { g_bmax[bid] = M; g_bsum[bid] = S; }
        }
    }
    grid_bar(nb);

    // ---------------- Phase 6: global LSE ------------------------------------
    if (bid == 0 && wid == 0) {
        float M = -INFINITY, S = 0.f;
        for (int i = lane; i < (int)nb; i += 32) lse_combine(M, S, g_bmax[i], g_bsum[i]);
#pragma unroll
        for (int o = 16; o > 0; o >>= 1) {
            float m2 = __shfl_down_sync(0xffffffffu, M, o);
            float s2 = __shfl_down_sync(0xffffffffu, S, o);
            lse_combine(M, S, m2, s2);
        }
        if (lane == 0) g_lse = M + logf(S);
    }
    grid_bar(nb);

    // ---------------- Phase 7: write log_probs from SMEM ---------------------
    {
        const float lse = g_lse;
        if (t < RSTAGE) out[bid * RSTAGE + t] = s_stlog[t] - lse;
        if (t < 32 * KMAX) {
            const int w = t / KMAX, k = t % KMAX;
            const int r = (bid * 32 + w) + k * totW;
            if (r < NREM) out[NSTAGED + r] = s_wlog[t] - lse;
        }
    }
}

extern "C" void kernel_launch(void* const* d_in, const int* in_sizes, int n_in,
                              void* d_out, int out_size) {
    const int*   ids    = (const int*)  d_in[0];
    const float* hidden = (const float*)d_in[1];
    const float* enc    = (const float*)d_in[2];
    const float* emb    = (const float*)d_in[3];
    const float* attn_W = (const float*)d_in[4];
    const float* attn_b = (const float*)d_in[5];
    const float* comb_W = (const float*)d_in[6];
    const float* comb_b = (const float*)d_in[7];
    const float* W_ih   = (const float*)d_in[8];
    const float* W_hh   = (const float*)d_in[9];
    const float* b_ih   = (const float*)d_in[10];
    const float* b_hh   = (const float*)d_in[11];
    const float* out_W  = (const float*)d_in[12];
    const float* out_b  = (const float*)d_in[13];
    float* out = (float*)d_out;

    int dev = 0, nsm = 148;
    cudaGetDevice(&dev);
    cudaDeviceGetAttribute(&nsm, cudaDevAttrMultiProcessorCount, dev);

    const int smem_bytes = RSTAGE * HH * sizeof(float);   // 176KB dynamic
    cudaFuncSetAttribute(fused_decoder,
                         cudaFuncAttributeMaxDynamicSharedMemorySize, smem_bytes);

    fused_decoder<<<nsm, 1024, smem_bytes>>>(ids, hidden, enc, emb, attn_W, attn_b,
                                             comb_W, comb_b, W_ih, W_hh, b_ih, b_hh,
                                             out_W, out_b, out);
}

// round 5
// speedup vs baseline: 1.1236x; 1.0331x over previous
#include <cuda_runtime.h>
#include <math.h>

#define HH 1024
#define LL 128
#define VOCAB 50257

// ---------------- device scratch (no allocations allowed) ----------------
__device__ float g_scores[LL];
__device__ float g_attn[HH];
__device__ float g_gru_in[HH];
__device__ float g_hnew[HH];
__device__ float g_ghr[HH], g_ghz[HH], g_ghn[HH];
__device__ float g_bmax[256], g_bsum[256];
__device__ float g_lse;
__device__ unsigned g_flags[256];   // per-block arrival generation
__device__ unsigned g_rel[16];      // per-barrier release word

__device__ __forceinline__ float warp_sum(float v) {
#pragma unroll
    for (int o = 16; o > 0; o >>= 1) v += __shfl_down_sync(0xffffffffu, v, o);
    return v;
}

// Store/poll grid barrier: plain-store arrival (no atomic contention),
// block 0 warp 0 sweeps flags and publishes g_rel[gen]; others poll it.
__device__ __forceinline__ void grid_bar(int nb, int bid, int t, int lane,
                                         int wid, unsigned gen) {
    __syncthreads();
    if (t == 0) {
        __threadfence();
        ((volatile unsigned*)g_flags)[bid] = gen;
    }
    if (bid == 0 && wid == 0) {
        bool ok;
        do {
            ok = true;
            for (int i = lane; i < nb; i += 32)
                if (((volatile unsigned*)g_flags)[i] < gen) ok = false;
            ok = __all_sync(0xffffffffu, ok);
        } while (!ok);
        if (lane == 0) {
            __threadfence();
            ((volatile unsigned*)g_rel)[gen] = 1u;
        }
    }
    if (t == 0) {
        while (((volatile unsigned*)g_rel)[gen] == 0u) {}
        __threadfence();
    }
    __syncthreads();
}

__device__ __forceinline__ void lse_combine(float& M, float& S, float m2, float s2) {
    if (m2 > M) { S = S * expf(M - m2) + s2; M = m2; }
    else        { S += s2 * expf(m2 - M); }
}

__global__ void __launch_bounds__(1024, 1)
fused_decoder(const int* __restrict__ ids,
              const float* __restrict__ hidden,
              const float* __restrict__ enc,
              const float* __restrict__ emb,
              const float* __restrict__ attn_W,
              const float* __restrict__ attn_b,
              const float* __restrict__ comb_W,
              const float* __restrict__ comb_b,
              const float* __restrict__ W_ih,
              const float* __restrict__ W_hh,
              const float* __restrict__ b_ih,
              const float* __restrict__ b_hh,
              const float* __restrict__ out_W,
              const float* __restrict__ out_b,
              float* __restrict__ out) {
    const int nb = gridDim.x;
    const int t = threadIdx.x, wid = t >> 5, lane = t & 31, bid = blockIdx.x;
    const int task = wid * nb + bid;        // warp-major task id for serial phases
    const int gw   = bid * 32 + wid;        // block-major warp id for logits
    const int totW = nb * 32;

    __shared__ float s_red[1024];
    __shared__ float s_h[HH];
    __shared__ float s_w[LL];
    __shared__ float s_m[2];
    __shared__ float s_bm[32], s_bs[32];

    const size_t qb = (size_t)ids[0] * HH;
    const float4* q4 = (const float4*)(emb + qb);
    const float4* h4 = (const float4*)hidden;

    // ---------------- Phase 0: gh = W_hh @ h (+bias), and attention scores ----
    if (task < HH) {
        const int j = task;
        const float4* wr = (const float4*)(W_hh + (size_t)j * HH);
        const float4* wz = (const float4*)(W_hh + (size_t)(j + HH) * HH);
        const float4* wn = (const float4*)(W_hh + (size_t)(j + 2 * HH) * HH);
        float ar = 0.f, az = 0.f, an = 0.f;
#pragma unroll
        for (int i = 0; i < 8; i++) {
            const int idx = lane + 32 * i;
            const float4 hv = h4[idx];
            float4 v;
            v = wr[idx]; ar += v.x*hv.x + v.y*hv.y + v.z*hv.z + v.w*hv.w;
            v = wz[idx]; az += v.x*hv.x + v.y*hv.y + v.z*hv.z + v.w*hv.w;
            v = wn[idx]; an += v.x*hv.x + v.y*hv.y + v.z*hv.z + v.w*hv.w;
        }
        ar = warp_sum(ar); az = warp_sum(az); an = warp_sum(an);
        if (lane == 0) {
            g_ghr[j] = ar + b_hh[j];
            g_ghz[j] = az + b_hh[j + HH];
            g_ghn[j] = an + b_hh[j + 2 * HH];
        }
    } else if (task < HH + LL) {
        const int l = task - HH;
        const float4* w = (const float4*)(attn_W + (size_t)l * 2 * HH);
        float acc = 0.f;
#pragma unroll
        for (int i = 0; i < 8; i++) {
            const int idx = lane + 32 * i;
            float4 a = w[idx],       b = q4[idx];
            acc += a.x*b.x + a.y*b.y + a.z*b.z + a.w*b.w;
            float4 c = w[idx + 256], d = h4[idx];
            acc += c.x*d.x + c.y*d.y + c.z*d.z + c.w*d.w;
        }
        acc = warp_sum(acc);
        if (lane == 0) g_scores[l] = acc + attn_b[l];
    }
    grid_bar(nb, bid, t, lane, wid, 1u);

    // ---------------- Phase 1: softmax + attn_applied (blocks 0..7) ----------
    if (bid < 8) {
        float sc = (t < LL) ? g_scores[t] : -INFINITY;
        if (t < LL) {
            float v = sc;
#pragma unroll
            for (int o = 16; o > 0; o >>= 1) v = fmaxf(v, __shfl_down_sync(0xffffffffu, v, o));
            if (lane == 0) s_bm[wid] = v;
        }
        __syncthreads();
        if (t == 0) s_m[0] = fmaxf(fmaxf(s_bm[0], s_bm[1]), fmaxf(s_bm[2], s_bm[3]));
        __syncthreads();
        float e = 0.f;
        if (t < LL) {
            e = expf(sc - s_m[0]);
            float v = warp_sum(e);
            if (lane == 0) s_bs[wid] = v;
        }
        __syncthreads();
        if (t == 0) s_m[1] = 1.f / (s_bs[0] + s_bs[1] + s_bs[2] + s_bs[3]);
        __syncthreads();
        if (t < LL) {
            s_w[t] = e * s_m[1];
            if (bid == 0) out[VOCAB + HH + t] = s_w[t];
        }
        __syncthreads();
        const int col = t & 127, lg = t >> 7;
        const int colg = bid * 128 + col;
        float acc = 0.f;
#pragma unroll
        for (int k = 0; k < 16; k++) {
            const int l = lg * 16 + k;
            acc += s_w[l] * enc[(size_t)l * HH + colg];
        }
        s_red[t] = acc;
        __syncthreads();
        if (t < 128) {
            float a = 0.f;
#pragma unroll
            for (int k = 0; k < 8; k++) a += s_red[t + 128 * k];
            g_attn[colg] = a;
        }
    }
    grid_bar(nb, bid, t, lane, wid, 2u);

    // ---------------- Phase 2: gru_in = relu([q; attn] @ comb_W.T + b) -------
    if (task < HH) {
        const int j = task;
        const float4* wr = (const float4*)(comb_W + (size_t)j * 2 * HH);
        const float4* a4 = (const float4*)g_attn;
        float acc = 0.f;
#pragma unroll
        for (int i = 0; i < 8; i++) {
            const int idx = lane + 32 * i;
            float4 a = wr[idx],       b = q4[idx];
            acc += a.x*b.x + a.y*b.y + a.z*b.z + a.w*b.w;
            float4 c = wr[idx + 256], d = a4[idx];
            acc += c.x*d.x + c.y*d.y + c.z*d.z + c.w*d.w;
        }
        acc = warp_sum(acc);
        if (lane == 0) g_gru_in[j] = fmaxf(acc + comb_b[j], 0.f);
    }
    grid_bar(nb, bid, t, lane, wid, 3u);

    // ---------------- Phase 3: gi = W_ih @ gru_in, + GRU gate math -----------
    if (task < HH) {
        const int j = task;
        const float4* wr = (const float4*)(W_ih + (size_t)j * HH);
        const float4* wz = (const float4*)(W_ih + (size_t)(j + HH) * HH);
        const float4* wn = (const float4*)(W_ih + (size_t)(j + 2 * HH) * HH);
        const float4* g4 = (const float4*)g_gru_in;
        float ar = 0.f, az = 0.f, an = 0.f;
#pragma unroll
        for (int i = 0; i < 8; i++) {
            const int idx = lane + 32 * i;
            const float4 gv = g4[idx];
            float4 v;
            v = wr[idx]; ar += v.x*gv.x + v.y*gv.y + v.z*gv.z + v.w*gv.w;
            v = wz[idx]; az += v.x*gv.x + v.y*gv.y + v.z*gv.z + v.w*gv.w;
            v = wn[idx]; an += v.x*gv.x + v.y*gv.y + v.z*gv.z + v.w*gv.w;
        }
        ar = warp_sum(ar); az = warp_sum(az); an = warp_sum(an);
        if (lane == 0) {
            const float ir  = ar + b_ih[j];
            const float iz  = az + b_ih[j + HH];
            const float inn = an + b_ih[j + 2 * HH];
            const float r = 1.f / (1.f + expf(-(ir + g_ghr[j])));
            const float z = 1.f / (1.f + expf(-(iz + g_ghz[j])));
            const float n = tanhf(inn + r * g_ghn[j]);
            const float hn = (1.f - z) * n + z * hidden[j];
            g_hnew[j] = hn;
            out[VOCAB + j] = hn;
        }
    }
    grid_bar(nb, bid, t, lane, wid, 4u);

    // ---------------- Phase 5: logits GEMV (206 MB), 2 rows/warp/iter --------
    {
        if (t < 256) ((float4*)s_h)[t] = ((const float4*)g_hnew)[t];
        __syncthreads();
        const float4* h4s = (const float4*)s_h;

        float m = -INFINITY, s = 0.f;
        int r = gw;
        for (; r + totW < VOCAB; r += 2 * totW) {
            const float4* w0 = (const float4*)(out_W + (size_t)r * HH);
            const float4* w1 = (const float4*)(out_W + (size_t)(r + totW) * HH);
            float a0 = 0.f, a1 = 0.f;
#pragma unroll
            for (int i = 0; i < 8; i++) {
                const int idx = lane + 32 * i;
                const float4 b = h4s[idx];
                const float4 x = w0[idx];
                const float4 y = w1[idx];
                a0 += x.x*b.x + x.y*b.y + x.z*b.z + x.w*b.w;
                a1 += y.x*b.x + y.y*b.y + y.z*b.z + y.w*b.w;
            }
            a0 = warp_sum(a0); a1 = warp_sum(a1);
            if (lane == 0) {
                const float l0 = a0 + out_b[r];
                const float l1 = a1 + out_b[r + totW];
                out[r] = l0; out[r + totW] = l1;
                lse_combine(m, s, l0, 1.f);
                lse_combine(m, s, l1, 1.f);
            }
        }
        for (; r < VOCAB; r += totW) {
            const float4* w0 = (const float4*)(out_W + (size_t)r * HH);
            float a0 = 0.f;
#pragma unroll
            for (int i = 0; i < 8; i++) {
                const int idx = lane + 32 * i;
                const float4 b = h4s[idx];
                const float4 x = w0[idx];
                a0 += x.x*b.x + x.y*b.y + x.z*b.z + x.w*b.w;
            }
            a0 = warp_sum(a0);
            if (lane == 0) {
                const float l0 = a0 + out_b[r];
                out[r] = l0;
                lse_combine(m, s, l0, 1.f);
            }
        }
        if (lane == 0) { s_bm[wid] = m; s_bs[wid] = s; }
        __syncthreads();
        if (wid == 0) {
            float M = s_bm[lane], S = s_bs[lane];
#pragma unroll
            for (int o = 16; o > 0; o >>= 1) {
                float m2 = __shfl_down_sync(0xffffffffu, M, o);
                float s2 = __shfl_down_sync(0xffffffffu, S, o);
                lse_combine(M, S, m2, s2);
            }
            if (lane == 0) { g_bmax[bid] = M; g_bsum[bid] = S; }
        }
    }
    grid_bar(nb, bid, t, lane, wid, 5u);

    // ---------------- Phase 6: global LSE ------------------------------------
    if (bid == 0 && wid == 0) {
        float M = -INFINITY, S = 0.f;
        for (int i = lane; i < nb; i += 32) lse_combine(M, S, g_bmax[i], g_bsum[i]);
#pragma unroll
        for (int o = 16; o > 0; o >>= 1) {
            float m2 = __shfl_down_sync(0xffffffffu, M, o);
            float s2 = __shfl_down_sync(0xffffffffu, S, o);
            lse_combine(M, S, m2, s2);
        }
        if (lane == 0) g_lse = M + logf(S);
    }
    grid_bar(nb, bid, t, lane, wid, 6u);

    // ---------------- Phase 7: log_probs = logits - lse ----------------------
    {
        const float lse = g_lse;
        for (int i = bid * 1024 + t; i < VOCAB; i += nb * 1024) out[i] -= lse;
    }

    // ---------------- Epilogue: reset barrier state for next graph replay ----
    __syncthreads();
    if (t == 0) {
        __threadfence();
        ((volatile unsigned*)g_flags)[bid] = 7u;   // arrival only; no release wait
    }
    if (bid == 0 && wid == 0) {
        bool ok;
        do {
            ok = true;
            for (int i = lane; i < nb; i += 32)
                if (((volatile unsigned*)g_flags)[i] < 7u) ok = false;
            ok = __all_sync(0xffffffffu, ok);
        } while (!ok);
        for (int i = lane; i < nb; i += 32) ((volatile unsigned*)g_flags)[i] = 0u;
        if (lane < 16) ((volatile unsigned*)g_rel)[lane] = 0u;
    }
}

extern "C" void kernel_launch(void* const* d_in, const int* in_sizes, int n_in,
                              void* d_out, int out_size) {
    const int*   ids    = (const int*)  d_in[0];
    const float* hidden = (const float*)d_in[1];
    const float* enc    = (const float*)d_in[2];
    const float* emb    = (const float*)d_in[3];
    const float* attn_W = (const float*)d_in[4];
    const float* attn_b = (const float*)d_in[5];
    const float* comb_W = (const float*)d_in[6];
    const float* comb_b = (const float*)d_in[7];
    const float* W_ih   = (const float*)d_in[8];
    const float* W_hh   = (const float*)d_in[9];
    const float* b_ih   = (const float*)d_in[10];
    const float* b_hh   = (const float*)d_in[11];
    const float* out_W  = (const float*)d_in[12];
    const float* out_b  = (const float*)d_in[13];
    float* out = (float*)d_out;

    int dev = 0, nsm = 148;
    cudaGetDevice(&dev);
    cudaDeviceGetAttribute(&nsm, cudaDevAttrMultiProcessorCount, dev);

    fused_decoder<<<nsm, 1024>>>(ids, hidden, enc, emb, attn_W, attn_b,
                                 comb_W, comb_b, W_ih, W_hh, b_ih, b_hh,
                                 out_W, out_b, out);
}